// round 2
// baseline (speedup 1.0000x reference)
#include <cuda_runtime.h>
#include <math.h>

#define Bsz 2
#define Sq  2048
#define Hd  2048
#define NH  16
#define HD  128           // head dim
#define MROWS (Bsz*Sq)    // 4096

// ---------------- static scratch (allocation-free) ----------------
__device__ float g_q[(size_t)Bsz*NH*Sq*HD];    // [b*NH+h][s][d]
__device__ float g_k[(size_t)Bsz*NH*Sq*HD];
__device__ float g_v[(size_t)Bsz*NH*Sq*HD];
__device__ float g_ctx[(size_t)Bsz*Sq*Hd];     // [b*S+s][h*HD+d] row-major

// ---------------- tiled fp32 GEMM: 128x128x16, 256 threads, 8x8/thread ----------------
#define BM 128
#define BN 128
#define BK 16

// C = X[M,K] @ W[K,N] + bias, epilogue scatters into g_q/g_k/g_v ([b*NH+h][s][d])
__global__ __launch_bounds__(256) void qkv_gemm_kernel(const float* __restrict__ X,
                                                       const float* __restrict__ W,
                                                       const float* __restrict__ bias) {
    __shared__ float As[BK][BM];   // transposed A tile: As[k][m]
    __shared__ float Bs[BK][BN];

    const int tid = threadIdx.x;
    const int tx = tid & 15, ty = tid >> 4;
    const int rowBase = blockIdx.y * BM;
    const int colBase = blockIdx.x * BN;
    const int K = Hd;          // 2048
    const int N = 3 * Hd;      // 6144

    float acc[8][8];
#pragma unroll
    for (int i = 0; i < 8; i++)
#pragma unroll
        for (int j = 0; j < 8; j++) acc[i][j] = 0.0f;

    for (int kb = 0; kb < K; kb += BK) {
        // load A 128x16 (transposed store)
#pragma unroll
        for (int q = 0; q < 2; q++) {
            int lin = tid + q * 256;              // 0..511
            int r = lin >> 2;
            int c4 = (lin & 3) * 4;
            float4 va = *(const float4*)&X[(size_t)(rowBase + r) * K + kb + c4];
            As[c4 + 0][r] = va.x;
            As[c4 + 1][r] = va.y;
            As[c4 + 2][r] = va.z;
            As[c4 + 3][r] = va.w;
        }
        // load B 16x128
#pragma unroll
        for (int q = 0; q < 2; q++) {
            int lin = tid + q * 256;
            int r = lin >> 5;                     // 0..15
            int c4 = (lin & 31) * 4;
            *(float4*)&Bs[r][c4] = *(const float4*)&W[(size_t)(kb + r) * N + colBase + c4];
        }
        __syncthreads();
#pragma unroll
        for (int kk = 0; kk < BK; kk++) {
            float a[8], b[8];
#pragma unroll
            for (int i = 0; i < 8; i++) a[i] = As[kk][ty * 8 + i];
#pragma unroll
            for (int j = 0; j < 8; j++) b[j] = Bs[kk][tx * 8 + j];
#pragma unroll
            for (int i = 0; i < 8; i++)
#pragma unroll
                for (int j = 0; j < 8; j++) acc[i][j] += a[i] * b[j];
        }
        __syncthreads();
    }

    // epilogue: scatter into q/k/v head-major layout
    const int which = colBase / Hd;            // 0=Q 1=K 2=V (tile never straddles)
    const int head = (colBase % Hd) / HD;      // tile never straddles a head
    float* dst = (which == 0) ? g_q : (which == 1) ? g_k : g_v;
#pragma unroll
    for (int i = 0; i < 8; i++) {
        int row = rowBase + ty * 8 + i;
        int b_ = row / Sq, s_ = row % Sq;
        size_t base = ((size_t)(b_ * NH + head) * Sq + s_) * HD;
#pragma unroll
        for (int j = 0; j < 8; j++) {
            int dloc = tx * 8 + j;             // 0..127 within head
            dst[base + dloc] = acc[i][j] + bias[colBase + dloc];
        }
    }
}

// out = g_ctx[M,K] @ W[K,N] + bias (plain row-major epilogue)
__global__ __launch_bounds__(256) void out_gemm_kernel(const float* __restrict__ W,
                                                       const float* __restrict__ bias,
                                                       float* __restrict__ out) {
    __shared__ float As[BK][BM];
    __shared__ float Bs[BK][BN];

    const int tid = threadIdx.x;
    const int tx = tid & 15, ty = tid >> 4;
    const int rowBase = blockIdx.y * BM;
    const int colBase = blockIdx.x * BN;
    const int K = Hd, N = Hd;

    float acc[8][8];
#pragma unroll
    for (int i = 0; i < 8; i++)
#pragma unroll
        for (int j = 0; j < 8; j++) acc[i][j] = 0.0f;

    for (int kb = 0; kb < K; kb += BK) {
#pragma unroll
        for (int q = 0; q < 2; q++) {
            int lin = tid + q * 256;
            int r = lin >> 2;
            int c4 = (lin & 3) * 4;
            float4 va = *(const float4*)&g_ctx[(size_t)(rowBase + r) * K + kb + c4];
            As[c4 + 0][r] = va.x;
            As[c4 + 1][r] = va.y;
            As[c4 + 2][r] = va.z;
            As[c4 + 3][r] = va.w;
        }
#pragma unroll
        for (int q = 0; q < 2; q++) {
            int lin = tid + q * 256;
            int r = lin >> 5;
            int c4 = (lin & 31) * 4;
            *(float4*)&Bs[r][c4] = *(const float4*)&W[(size_t)(kb + r) * N + colBase + c4];
        }
        __syncthreads();
#pragma unroll
        for (int kk = 0; kk < BK; kk++) {
            float a[8], b[8];
#pragma unroll
            for (int i = 0; i < 8; i++) a[i] = As[kk][ty * 8 + i];
#pragma unroll
            for (int j = 0; j < 8; j++) b[j] = Bs[kk][tx * 8 + j];
#pragma unroll
            for (int i = 0; i < 8; i++)
#pragma unroll
                for (int j = 0; j < 8; j++) acc[i][j] += a[i] * b[j];
        }
        __syncthreads();
    }

#pragma unroll
    for (int i = 0; i < 8; i++) {
        int row = rowBase + ty * 8 + i;
#pragma unroll
        for (int j = 0; j < 8; j++) {
            int col = colBase + tx * 8 + j;
            out[(size_t)row * N + col] = acc[i][j] + bias[col];
        }
    }
}

// ---------------- flash attention, fp32, 64 queries x 64 keys tiles ----------------
// smem layout strides (floats), padded against bank conflicts
#define LQ 129
#define LK 129
#define LV 128
#define LP 65
#define SMEM_ATTN ((64*LQ + 64*LK + 64*LV + 64*LP) * 4)

__global__ void attn_kernel(const float* __restrict__ mask) {
    extern __shared__ float sm[];
    float* Qs = sm;                 // 64 x LQ
    float* Ks = Qs + 64 * LQ;       // 64 x LK
    float* Vs = Ks + 64 * LK;       // 64 x LV
    float* Ps = Vs + 64 * LV;       // 64 x LP

    const int tid = threadIdx.x;
    const int tx = tid & 15, ty = tid >> 4;
    const int bh = blockIdx.y;              // 0..B*NH-1
    const int b_ = bh / NH;
    const int head = bh % NH;
    const int q0 = blockIdx.x * 64;
    const float scale = 0.08838834764831845f;   // 1/sqrt(128)

    const float* Qg = g_q + (size_t)bh * Sq * HD;
    const float* Kg = g_k + (size_t)bh * Sq * HD;
    const float* Vg = g_v + (size_t)bh * Sq * HD;

    // load Q tile (pre-scaled): 64x128 = 2048 float4
    for (int lin = tid; lin < 2048; lin += 256) {
        int r = lin >> 5;
        int c4 = (lin & 31) * 4;
        float4 v = *(const float4*)&Qg[(size_t)(q0 + r) * HD + c4];
        Qs[r * LQ + c4 + 0] = v.x * scale;
        Qs[r * LQ + c4 + 1] = v.y * scale;
        Qs[r * LQ + c4 + 2] = v.z * scale;
        Qs[r * LQ + c4 + 3] = v.w * scale;
    }

    float m_r[4], l_r[4];
    float acc[4][8];
#pragma unroll
    for (int i = 0; i < 4; i++) {
        m_r[i] = -1e30f;
        l_r[i] = 0.0f;
#pragma unroll
        for (int j = 0; j < 8; j++) acc[i][j] = 0.0f;
    }

    for (int kt = 0; kt < Sq; kt += 64) {
        __syncthreads();   // Q ready (first iter) / prev PV done reading Vs,Ps
        // load K,V tiles (64x128 each)
        for (int lin = tid; lin < 2048; lin += 256) {
            int r = lin >> 5;
            int c4 = (lin & 31) * 4;
            float4 kv = *(const float4*)&Kg[(size_t)(kt + r) * HD + c4];
            Ks[r * LK + c4 + 0] = kv.x;
            Ks[r * LK + c4 + 1] = kv.y;
            Ks[r * LK + c4 + 2] = kv.z;
            Ks[r * LK + c4 + 3] = kv.w;
            *(float4*)&Vs[r * LV + c4] = *(const float4*)&Vg[(size_t)(kt + r) * HD + c4];
        }
        __syncthreads();

        // S tile 4x4 per thread: rows ty*4+i, cols tx*4+j
        float sv[4][4];
#pragma unroll
        for (int i = 0; i < 4; i++)
#pragma unroll
            for (int j = 0; j < 4; j++) sv[i][j] = 0.0f;

        for (int d = 0; d < HD; d++) {
            float a_[4], b_[4];
#pragma unroll
            for (int i = 0; i < 4; i++) a_[i] = Qs[(ty * 4 + i) * LQ + d];
#pragma unroll
            for (int j = 0; j < 4; j++) b_[j] = Ks[(tx * 4 + j) * LK + d];
#pragma unroll
            for (int i = 0; i < 4; i++)
#pragma unroll
                for (int j = 0; j < 4; j++) sv[i][j] += a_[i] * b_[j];
        }
        // additive mask (broadcast over queries)
        float mk[4];
#pragma unroll
        for (int j = 0; j < 4; j++) mk[j] = mask[b_ * Sq + kt + tx * 4 + j];
#pragma unroll
        for (int i = 0; i < 4; i++)
#pragma unroll
            for (int j = 0; j < 4; j++) sv[i][j] += mk[j];

        // online softmax per row (reduce over 16 tx lanes, width-16 groups)
#pragma unroll
        for (int i = 0; i < 4; i++) {
            float rmax = sv[i][0];
#pragma unroll
            for (int j = 1; j < 4; j++) rmax = fmaxf(rmax, sv[i][j]);
#pragma unroll
            for (int off = 8; off >= 1; off >>= 1)
                rmax = fmaxf(rmax, __shfl_xor_sync(0xffffffffu, rmax, off, 16));
            float newm = fmaxf(m_r[i], rmax);
            float alpha = __expf(m_r[i] - newm);
            float rsum = 0.0f;
#pragma unroll
            for (int j = 0; j < 4; j++) {
                sv[i][j] = __expf(sv[i][j] - newm);
                rsum += sv[i][j];
            }
#pragma unroll
            for (int off = 8; off >= 1; off >>= 1)
                rsum += __shfl_xor_sync(0xffffffffu, rsum, off, 16);
            l_r[i] = l_r[i] * alpha + rsum;
            m_r[i] = newm;
#pragma unroll
            for (int j = 0; j < 8; j++) acc[i][j] *= alpha;
#pragma unroll
            for (int j = 0; j < 4; j++)
                Ps[(ty * 4 + i) * LP + tx * 4 + j] = sv[i][j];
        }
        __syncthreads();

        // O += P @ V  (O cols tx*8..tx*8+7)
        for (int kk = 0; kk < 64; kk++) {
            float p_[4];
#pragma unroll
            for (int i = 0; i < 4; i++) p_[i] = Ps[(ty * 4 + i) * LP + kk];
            float4 v0 = *(float4*)&Vs[kk * LV + tx * 8];
            float4 v1 = *(float4*)&Vs[kk * LV + tx * 8 + 4];
#pragma unroll
            for (int i = 0; i < 4; i++) {
                acc[i][0] += p_[i] * v0.x;
                acc[i][1] += p_[i] * v0.y;
                acc[i][2] += p_[i] * v0.z;
                acc[i][3] += p_[i] * v0.w;
                acc[i][4] += p_[i] * v1.x;
                acc[i][5] += p_[i] * v1.y;
                acc[i][6] += p_[i] * v1.z;
                acc[i][7] += p_[i] * v1.w;
            }
        }
    }

    // normalize + write ctx [b*S+s][head*HD + col]
#pragma unroll
    for (int i = 0; i < 4; i++) {
        int r = q0 + ty * 4 + i;
        float inv = 1.0f / l_r[i];
        size_t base = ((size_t)b_ * Sq + r) * Hd + head * HD + tx * 8;
#pragma unroll
        for (int j = 0; j < 8; j++)
            g_ctx[base + j] = acc[i][j] * inv;
    }
}

// ---------------- launch ----------------
extern "C" void kernel_launch(void* const* d_in, const int* in_sizes, int n_in,
                              void* d_out, int out_size) {
    const float* X    = (const float*)d_in[0];   // hidden_states [B,S,H]
    const float* mask = (const float*)d_in[1];   // [B,1,1,S]
    const float* Wqkv = (const float*)d_in[2];   // [H, 3H]
    const float* bqkv = (const float*)d_in[3];   // [3H]
    const float* Wout = (const float*)d_in[4];   // [H, H]
    const float* bout = (const float*)d_in[5];   // [H]
    float* out = (float*)d_out;                  // [B,S,H]
    (void)in_sizes; (void)n_in; (void)out_size;

    cudaFuncSetAttribute(attn_kernel, cudaFuncAttributeMaxDynamicSharedMemorySize, SMEM_ATTN);

    // 1) QKV projection: [4096,2048] @ [2048,6144]
    {
        dim3 grid(3 * Hd / BN, MROWS / BM);   // (48, 32)
        qkv_gemm_kernel<<<grid, 256>>>(X, Wqkv, bqkv);
    }
    // 2) flash attention per (b,h) x 64-query tile
    {
        dim3 grid(Sq / 64, Bsz * NH);         // (32, 32)
        attn_kernel<<<grid, 256, SMEM_ATTN>>>(mask);
    }
    // 3) output projection: [4096,2048] @ [2048,2048]
    {
        dim3 grid(Hd / BN, MROWS / BM);       // (16, 32)
        out_gemm_kernel<<<grid, 256>>>(Wout, bout, out);
    }
}

// round 7
// speedup vs baseline: 1.4825x; 1.4825x over previous
#include <cuda_runtime.h>
#include <cuda_bf16.h>
#include <cstdint>
#include <math.h>

#define Bsz 2
#define Sq  2048
#define Hd  2048
#define NH  16
#define HD  128
#define MROWS (Bsz*Sq)    // 4096
#define GK   2048         // K dim of both GEMMs
#define BKC  32           // K per chunk
#define NCH  (GK/BKC)     // 64

// ---------------- static scratch (allocation-free) ----------------
__device__ float g_q[(size_t)Bsz*NH*Sq*HD];
__device__ float g_k[(size_t)Bsz*NH*Sq*HD];
__device__ float g_v[(size_t)Bsz*NH*Sq*HD];
__device__ float g_ctx[(size_t)Bsz*Sq*Hd];

__device__ __nv_bfloat16 g_xh[(size_t)MROWS*Hd];
__device__ __nv_bfloat16 g_xl[(size_t)MROWS*Hd];
__device__ __nv_bfloat16 g_wqt_h[(size_t)3*Hd*Hd];   // W_qkv^T  [6144, 2048]
__device__ __nv_bfloat16 g_wqt_l[(size_t)3*Hd*Hd];
__device__ __nv_bfloat16 g_wot_h[(size_t)Hd*Hd];     // W_out^T  [2048, 2048]
__device__ __nv_bfloat16 g_wot_l[(size_t)Hd*Hd];
__device__ __nv_bfloat16 g_ch[(size_t)MROWS*Hd];
__device__ __nv_bfloat16 g_cl[(size_t)MROWS*Hd];

// ---------------- helpers ----------------
__device__ __forceinline__ uint32_t smem_u32(const void* p) {
    uint32_t a;
    asm("{ .reg .u64 t; cvta.to.shared.u64 t, %1; cvt.u32.u64 %0, t; }" : "=r"(a) : "l"(p));
    return a;
}
__device__ __forceinline__ void cp16(uint32_t dst, const void* src) {
    asm volatile("cp.async.cg.shared.global [%0], [%1], 16;" :: "r"(dst), "l"(src) : "memory");
}
#define CP_COMMIT() asm volatile("cp.async.commit_group;" ::: "memory")

#define MMA16816(c, a, b)                                                         \
    asm volatile("mma.sync.aligned.m16n8k16.row.col.f32.bf16.bf16.f32 "           \
        "{%0,%1,%2,%3}, {%4,%5,%6,%7}, {%8,%9}, {%0,%1,%2,%3};"                   \
        : "+f"((c)[0]), "+f"((c)[1]), "+f"((c)[2]), "+f"((c)[3])                  \
        : "r"((a)[0]), "r"((a)[1]), "r"((a)[2]), "r"((a)[3]),                     \
          "r"((b)[0]), "r"((b)[1]))

// ---------------- conversion kernels ----------------
__global__ void conv_hl_kernel(const float* __restrict__ xin, int n, int which) {
    const float* x = which ? g_ctx : xin;
    __nv_bfloat16* h = which ? g_ch : g_xh;
    __nv_bfloat16* l = which ? g_cl : g_xl;
    int i = (blockIdx.x * blockDim.x + threadIdx.x) * 4;
    if (i >= n) return;
    float4 v = *(const float4*)(x + i);
    float f[4] = {v.x, v.y, v.z, v.w};
    __nv_bfloat16 hh[4], ll[4];
#pragma unroll
    for (int j = 0; j < 4; j++) {
        hh[j] = __float2bfloat16(f[j]);
        ll[j] = __float2bfloat16(f[j] - __bfloat162float(hh[j]));
    }
    *(uint2*)(h + i) = *(uint2*)hh;
    *(uint2*)(l + i) = *(uint2*)ll;
}

// W [K,N] fp32 -> W^T [N,K] bf16 hi/lo
__global__ void transpose_conv_kernel(const float* __restrict__ W, int N, int which) {
    __nv_bfloat16* Th = which ? g_wot_h : g_wqt_h;
    __nv_bfloat16* Tl = which ? g_wot_l : g_wqt_l;
    __shared__ float t[32][33];
    int nb = blockIdx.x * 32, kb = blockIdx.y * 32;
    int tx = threadIdx.x, ty = threadIdx.y;   // 32 x 8
#pragma unroll
    for (int j = 0; j < 32; j += 8)
        t[ty + j][tx] = W[(size_t)(kb + ty + j) * N + nb + tx];
    __syncthreads();
#pragma unroll
    for (int j = 0; j < 32; j += 8) {
        float x = t[tx][ty + j];
        __nv_bfloat16 h = __float2bfloat16(x);
        __nv_bfloat16 lo = __float2bfloat16(x - __bfloat162float(h));
        size_t o = (size_t)(nb + ty + j) * GK + kb + tx;
        Th[o] = h; Tl[o] = lo;
    }
}

// ---------------- mma.sync split-bf16 GEMM ----------------
// SMEM: per stage 4 tiles (Ah, Al, Bh, Bl), each 128 rows x 32 bf16, row stride
// padded to 80 B (40 bf16) -> conflict-free 32-bit fragment loads.
#define ROWB   80
#define TILEB  (128*ROWB)        // 10240 B
#define STAGEB (4*TILEB)         // 40960 B
#define SMEM_MMA (2*STAGEB)      // 81920 B

// mode 0: C = X @ Wqkv + b, scatter to g_q/g_k/g_v.  mode 1: C = ctx @ Wout + b -> outp
__global__ __launch_bounds__(256, 2) void mma_gemm_kernel(const float* __restrict__ bias,
                                                          float* __restrict__ outp,
                                                          int Nglob, int mode) {
    extern __shared__ __align__(16) char smc[];
    const uint32_t sb = smem_u32(smc);
    const int tid  = threadIdx.x;
    const int lane = tid & 31, warp = tid >> 5;
    const int wm = warp & 1;            // 2 warps along M (64 rows each)
    const int wn = warp >> 1;           // 4 warps along N (32 cols each)
    const int g = lane >> 2, t = lane & 3;
    const int rowBase = blockIdx.y * 128;
    const int colBase = blockIdx.x * 128;

    const __nv_bfloat16* Ah_g = mode ? g_ch : g_xh;
    const __nv_bfloat16* Al_g = mode ? g_cl : g_xl;
    const __nv_bfloat16* Bh_g = mode ? g_wot_h : g_wqt_h;
    const __nv_bfloat16* Bl_g = mode ? g_wot_l : g_wqt_l;

    float acc[4][4][4];
#pragma unroll
    for (int mt = 0; mt < 4; mt++)
#pragma unroll
        for (int nt = 0; nt < 4; nt++)
#pragma unroll
            for (int c = 0; c < 4; c++) acc[mt][nt][c] = 0.0f;

    auto issue_stage = [&](int s, int chunk) {
        const int kb = chunk * BKC;
        const uint32_t stg = sb + s * STAGEB;
#pragma unroll
        for (int j = 0; j < 8; j++) {
            int id = tid + j * 256;          // 0..2047
            int tile = id >> 9;              // 0..3
            int rem = id & 511;
            int r = rem >> 2, c = rem & 3;   // r 0..127, c 0..3 (16B chunks)
            const __nv_bfloat16* src;
            if (tile == 0)      src = Ah_g + (size_t)(rowBase + r) * GK + kb + c * 8;
            else if (tile == 1) src = Al_g + (size_t)(rowBase + r) * GK + kb + c * 8;
            else if (tile == 2) src = Bh_g + (size_t)(colBase + r) * GK + kb + c * 8;
            else                src = Bl_g + (size_t)(colBase + r) * GK + kb + c * 8;
            cp16(stg + tile * TILEB + r * ROWB + c * 16, src);
        }
        CP_COMMIT();
    };

    issue_stage(0, 0);

    for (int i = 0; i < NCH; i++) {
        const int s = i & 1;
        if (i + 1 < NCH) {
            issue_stage(s ^ 1, i + 1);
            asm volatile("cp.async.wait_group 1;" ::: "memory");
        } else {
            asm volatile("cp.async.wait_group 0;" ::: "memory");
        }
        __syncthreads();

        const char* stg = smc + s * STAGEB;
#pragma unroll
        for (int ks = 0; ks < 2; ks++) {
            uint32_t ah[4][4], al[4][4];
#pragma unroll
            for (int mt = 0; mt < 4; mt++) {
                const char* p = stg + (wm * 64 + mt * 16 + g) * ROWB + ks * 32 + t * 4;
                ah[mt][0] = *(const uint32_t*)(p);
                ah[mt][1] = *(const uint32_t*)(p + 8 * ROWB);
                ah[mt][2] = *(const uint32_t*)(p + 16);
                ah[mt][3] = *(const uint32_t*)(p + 8 * ROWB + 16);
                const char* q = p + TILEB;
                al[mt][0] = *(const uint32_t*)(q);
                al[mt][1] = *(const uint32_t*)(q + 8 * ROWB);
                al[mt][2] = *(const uint32_t*)(q + 16);
                al[mt][3] = *(const uint32_t*)(q + 8 * ROWB + 16);
            }
#pragma unroll
            for (int nt = 0; nt < 4; nt++) {
                const char* p = stg + 2 * TILEB + (wn * 32 + nt * 8 + g) * ROWB + ks * 32 + t * 4;
                uint32_t bh[2], bl[2];
                bh[0] = *(const uint32_t*)(p);
                bh[1] = *(const uint32_t*)(p + 16);
                bl[0] = *(const uint32_t*)(p + TILEB);
                bl[1] = *(const uint32_t*)(p + TILEB + 16);
#pragma unroll
                for (int mt = 0; mt < 4; mt++) {
                    MMA16816(acc[mt][nt], ah[mt], bh);
                    MMA16816(acc[mt][nt], al[mt], bh);
                    MMA16816(acc[mt][nt], ah[mt], bl);
                }
            }
        }
        __syncthreads();
    }

    // epilogue
    const int which = colBase / Hd;
    const int head = (colBase % Hd) / HD;
    float* qkv_dst = (which == 0) ? g_q : (which == 1) ? g_k : g_v;
#pragma unroll
    for (int mt = 0; mt < 4; mt++) {
        const int r0 = rowBase + wm * 64 + mt * 16 + g;
#pragma unroll
        for (int nt = 0; nt < 4; nt++) {
            const int local = wn * 32 + nt * 8 + t * 2;     // 0..127 in tile
            const int c0 = colBase + local;
            const float b0 = bias[c0], b1 = bias[c0 + 1];
#pragma unroll
            for (int half = 0; half < 2; half++) {
                const int rr = r0 + half * 8;
                const float v0 = acc[mt][nt][half * 2 + 0] + b0;
                const float v1 = acc[mt][nt][half * 2 + 1] + b1;
                if (mode == 0) {
                    const int b_ = rr / Sq, s_ = rr % Sq;
                    size_t base = ((size_t)(b_ * NH + head) * Sq + s_) * (size_t)HD + local;
                    qkv_dst[base]     = v0;
                    qkv_dst[base + 1] = v1;
                } else {
                    size_t base = (size_t)rr * Nglob + c0;
                    outp[base]     = v0;
                    outp[base + 1] = v1;
                }
            }
        }
    }
}

// ---------------- flash attention (SIMT fp32, unchanged) ----------------
#define LQ 129
#define LK 129
#define LV 128
#define LP 65
#define SMEM_ATTN ((64*LQ + 64*LK + 64*LV + 64*LP) * 4)

__global__ void attn_kernel(const float* __restrict__ mask) {
    extern __shared__ float sm[];
    float* Qs = sm;
    float* Ks = Qs + 64 * LQ;
    float* Vs = Ks + 64 * LK;
    float* Ps = Vs + 64 * LV;

    const int tid = threadIdx.x;
    const int tx = tid & 15, ty = tid >> 4;
    const int bh = blockIdx.y;
    const int b_ = bh / NH;
    const int q0 = blockIdx.x * 64;
    const float scale = 0.08838834764831845f;

    const float* Qg = g_q + (size_t)bh * Sq * HD;
    const float* Kg = g_k + (size_t)bh * Sq * HD;
    const float* Vg = g_v + (size_t)bh * Sq * HD;
    const int head = bh % NH;

    for (int lin = tid; lin < 2048; lin += 256) {
        int r = lin >> 5;
        int c4 = (lin & 31) * 4;
        float4 v = *(const float4*)&Qg[(size_t)(q0 + r) * HD + c4];
        Qs[r * LQ + c4 + 0] = v.x * scale;
        Qs[r * LQ + c4 + 1] = v.y * scale;
        Qs[r * LQ + c4 + 2] = v.z * scale;
        Qs[r * LQ + c4 + 3] = v.w * scale;
    }

    float m_r[4], l_r[4];
    float acc[4][8];
#pragma unroll
    for (int i = 0; i < 4; i++) {
        m_r[i] = -1e30f;
        l_r[i] = 0.0f;
#pragma unroll
        for (int j = 0; j < 8; j++) acc[i][j] = 0.0f;
    }

    for (int kt = 0; kt < Sq; kt += 64) {
        __syncthreads();
        for (int lin = tid; lin < 2048; lin += 256) {
            int r = lin >> 5;
            int c4 = (lin & 31) * 4;
            float4 kv = *(const float4*)&Kg[(size_t)(kt + r) * HD + c4];
            Ks[r * LK + c4 + 0] = kv.x;
            Ks[r * LK + c4 + 1] = kv.y;
            Ks[r * LK + c4 + 2] = kv.z;
            Ks[r * LK + c4 + 3] = kv.w;
            *(float4*)&Vs[r * LV + c4] = *(const float4*)&Vg[(size_t)(kt + r) * HD + c4];
        }
        __syncthreads();

        float sv[4][4];
#pragma unroll
        for (int i = 0; i < 4; i++)
#pragma unroll
            for (int j = 0; j < 4; j++) sv[i][j] = 0.0f;

        for (int d = 0; d < HD; d++) {
            float a_[4], b_v[4];
#pragma unroll
            for (int i = 0; i < 4; i++) a_[i] = Qs[(ty * 4 + i) * LQ + d];
#pragma unroll
            for (int j = 0; j < 4; j++) b_v[j] = Ks[(tx * 4 + j) * LK + d];
#pragma unroll
            for (int i = 0; i < 4; i++)
#pragma unroll
                for (int j = 0; j < 4; j++) sv[i][j] += a_[i] * b_v[j];
        }
        float mk[4];
#pragma unroll
        for (int j = 0; j < 4; j++) mk[j] = mask[b_ * Sq + kt + tx * 4 + j];
#pragma unroll
        for (int i = 0; i < 4; i++)
#pragma unroll
            for (int j = 0; j < 4; j++) sv[i][j] += mk[j];

#pragma unroll
        for (int i = 0; i < 4; i++) {
            float rmax = sv[i][0];
#pragma unroll
            for (int j = 1; j < 4; j++) rmax = fmaxf(rmax, sv[i][j]);
#pragma unroll
            for (int off = 8; off >= 1; off >>= 1)
                rmax = fmaxf(rmax, __shfl_xor_sync(0xffffffffu, rmax, off, 16));
            float newm = fmaxf(m_r[i], rmax);
            float alpha = __expf(m_r[i] - newm);
            float rsum = 0.0f;
#pragma unroll
            for (int j = 0; j < 4; j++) {
                sv[i][j] = __expf(sv[i][j] - newm);
                rsum += sv[i][j];
            }
#pragma unroll
            for (int off = 8; off >= 1; off >>= 1)
                rsum += __shfl_xor_sync(0xffffffffu, rsum, off, 16);
            l_r[i] = l_r[i] * alpha + rsum;
            m_r[i] = newm;
#pragma unroll
            for (int j = 0; j < 8; j++) acc[i][j] *= alpha;
#pragma unroll
            for (int j = 0; j < 4; j++)
                Ps[(ty * 4 + i) * LP + tx * 4 + j] = sv[i][j];
        }
        __syncthreads();

        for (int kk = 0; kk < 64; kk++) {
            float p_[4];
#pragma unroll
            for (int i = 0; i < 4; i++) p_[i] = Ps[(ty * 4 + i) * LP + kk];
            float4 v0 = *(float4*)&Vs[kk * LV + tx * 8];
            float4 v1 = *(float4*)&Vs[kk * LV + tx * 8 + 4];
#pragma unroll
            for (int i = 0; i < 4; i++) {
                acc[i][0] += p_[i] * v0.x;
                acc[i][1] += p_[i] * v0.y;
                acc[i][2] += p_[i] * v0.z;
                acc[i][3] += p_[i] * v0.w;
                acc[i][4] += p_[i] * v1.x;
                acc[i][5] += p_[i] * v1.y;
                acc[i][6] += p_[i] * v1.z;
                acc[i][7] += p_[i] * v1.w;
            }
        }
    }

#pragma unroll
    for (int i = 0; i < 4; i++) {
        int r = q0 + ty * 4 + i;
        float inv = 1.0f / l_r[i];
        size_t base = ((size_t)b_ * Sq + r) * Hd + head * HD + tx * 8;
#pragma unroll
        for (int j = 0; j < 8; j++)
            g_ctx[base + j] = acc[i][j] * inv;
    }
}

// ---------------- launch ----------------
extern "C" void kernel_launch(void* const* d_in, const int* in_sizes, int n_in,
                              void* d_out, int out_size) {
    const float* X    = (const float*)d_in[0];
    const float* mask = (const float*)d_in[1];
    const float* Wqkv = (const float*)d_in[2];
    const float* bqkv = (const float*)d_in[3];
    const float* Wout = (const float*)d_in[4];
    const float* bout = (const float*)d_in[5];
    float* out = (float*)d_out;
    (void)in_sizes; (void)n_in; (void)out_size;

    cudaFuncSetAttribute(attn_kernel, cudaFuncAttributeMaxDynamicSharedMemorySize, SMEM_ATTN);
    cudaFuncSetAttribute(mma_gemm_kernel, cudaFuncAttributeMaxDynamicSharedMemorySize, SMEM_MMA);

    // 1) convert X -> bf16 hi/lo
    {
        int n = MROWS * Hd;
        conv_hl_kernel<<<n / 4 / 256, 256>>>(X, n, 0);
    }
    // 2) transpose+convert weights
    {
        dim3 g(3 * Hd / 32, Hd / 32), b(32, 8);
        transpose_conv_kernel<<<g, b>>>(Wqkv, 3 * Hd, 0);
    }
    {
        dim3 g(Hd / 32, Hd / 32), b(32, 8);
        transpose_conv_kernel<<<g, b>>>(Wout, Hd, 1);
    }
    // 3) QKV projection on tensor cores (mma.sync)
    {
        dim3 grid(3 * Hd / 128, MROWS / 128);   // (48, 32)
        mma_gemm_kernel<<<grid, 256, SMEM_MMA>>>(bqkv, nullptr, 3 * Hd, 0);
    }
    // 4) flash attention (SIMT)
    {
        dim3 grid(Sq / 64, Bsz * NH);
        attn_kernel<<<grid, 256, SMEM_ATTN>>>(mask);
    }
    // 5) convert ctx -> bf16 hi/lo
    {
        int n = MROWS * Hd;
        conv_hl_kernel<<<n / 4 / 256, 256>>>(nullptr, n, 1);
    }
    // 6) output projection on tensor cores (mma.sync)
    {
        dim3 grid(Hd / 128, MROWS / 128);       // (16, 32)
        mma_gemm_kernel<<<grid, 256, SMEM_MMA>>>(bout, out, Hd, 1);
    }
}